// round 15
// baseline (speedup 1.0000x reference)
#include <cuda_runtime.h>
#include <math_constants.h>

#define NB   32
#define LT   2048
#define CC   128
#define J    64          // chunks along L (one block per chunk)
#define TC   (LT / J)    // 32 rows per chunk
#define OUTW 1172        // 3*384 + 20
#define NLC  ((size_t)NB * LT * CC)          // 8,388,608
#define OUT_ELEMS ((size_t)NB * LT * OUTW)   // 76,808,192
#define NCH  (3 * NB * J)                    // 6144 chunk-blocks

// decoupled-lookback state. key = orderedFloat(max) << 32 | (2047 - argmax)
__device__ unsigned long long g_lkey[NCH * CC], g_ikey[NCH * CC];
__device__ float g_lsum[NCH * CC], g_isum[NCH * CC];
__device__ int   g_flag[NCH];

__global__ void init_kernel() {
    int t = blockIdx.x * 256 + threadIdx.x;
    if (t < NCH) g_flag[t] = 0;
}

__device__ __forceinline__ unsigned long long pack_key(float m, int a) {
    unsigned int b = __float_as_uint(m);
    b ^= (b & 0x80000000u) ? 0xFFFFFFFFu : 0x80000000u;   // order-preserving
    return ((unsigned long long)b << 32) | (unsigned)(2047 - a);
}
__device__ __forceinline__ void unpack_key(unsigned long long k, float& m, int& a) {
    unsigned int b = (unsigned int)(k >> 32);
    b ^= (b & 0x80000000u) ? 0x80000000u : 0xFFFFFFFFu;
    m = __uint_as_float(b);
    a = 2047 - (int)(k & 0xFFFFFFFFu);
}

__global__ void __launch_bounds__(128) fused_kernel(const float* __restrict__ x0,
                                                    const float* __restrict__ x1,
                                                    const float* __restrict__ x2,
                                                    const float* __restrict__ dem,
                                                    const float* __restrict__ W1,
                                                    const float* __restrict__ b1,
                                                    const float* __restrict__ W2,
                                                    const float* __restrict__ b2,
                                                    float* __restrict__ out) {
    const int j = blockIdx.x, n = blockIdx.y, i = blockIdx.z;
    const int c = threadIdx.x;                    // one channel per thread
    const int l = c & 31;                         // lane
    const float* x = (i == 0) ? x0 : (i == 1) ? x1 : x2;
    const int chain = i * NB + n;
    const int b = chain * J + j;

    __shared__ float h_sh[40];
    __shared__ float d_sh[20];

    // -- demographic MLP (used by i==0 blocks; recomputed per block) ----------
    if (i == 0 && c < 40) {
        float s = b1[c];
#pragma unroll
        for (int k = 0; k < 8; ++k) s = fmaf(dem[n * 8 + k], W1[k * 40 + c], s);
        h_sh[c] = fmaxf(s, 0.f);
    }
    __syncthreads();
    if (i == 0 && c < 20) {
        float s = b2[c];
#pragma unroll
        for (int k = 0; k < 40; ++k) s = fmaf(h_sh[k], W2[k * 20 + c], s);
        d_sh[c] = fmaxf(s, 0.f);
    }

    // -- phase 1: load my chunk once, compute local aggregate -----------------
    const size_t row0 = (size_t)n * LT + (size_t)j * TC;
    const float* p = x + row0 * CC + c;

    float lm = -CUDART_INF_F, ls = 0.f;
    int la = 0;
#pragma unroll 8
    for (int t = 0; t < TC; ++t) {
        float v = p[(size_t)t * CC];              // allocates in L1 for phase 3
        ls += v;
        if (v > lm) { lm = v; la = j * TC + t; }  // strict > => earliest wins
    }
    const unsigned long long lkey = pack_key(lm, la);

    // -- publish local aggregate (flag = 1) via release store -----------------
    if (j > 0) {
        g_lkey[b * CC + c] = lkey;
        g_lsum[b * CC + c] = ls;
        __syncthreads();                          // block stores happen-before release
        if (c == 0)
            asm volatile("st.release.gpu.global.b32 [%0], %1;"
                         :: "l"(&g_flag[b]), "r"(1) : "memory");
    }

    // -- parallel-window decoupled lookback: exclusive prefix over 0..j-1 -----
    unsigned long long pkey = pack_key(-CUDART_INF_F, 0);
    float ps = 0.f;
    if (j > 0) {
        int kHigh = j - 1;
        for (;;) {
            int kLow = kHigh - 31; if (kLow < 0) kLow = 0;
            const int nk = kHigh - kLow + 1;
            const int myk = kHigh - l;
            int f = 0;
            if (l < nk) {
                do { f = *(volatile int*)&g_flag[chain * J + myk]; } while (f == 0);
            }
            const unsigned m2 = __ballot_sync(0xFFFFFFFFu, (l < nk) && (f == 2));
            __threadfence();                      // acquire: value reads ordered after flags
            int stopK = -1;
            if (m2) stopK = kHigh - (__ffs(m2) - 1);   // most recent INCLUSIVE in window
            const int kEnd = (stopK >= 0) ? stopK : kLow;
#pragma unroll 4
            for (int k = kHigh; k >= kEnd; --k) {
                const int idx = (chain * J + k) * CC + c;
                unsigned long long kk;
                float sv;
                if (k == stopK) { kk = __ldcg(&g_ikey[idx]); sv = __ldcg(&g_isum[idx]); }
                else            { kk = __ldcg(&g_lkey[idx]); sv = __ldcg(&g_lsum[idx]); }
                if (kk > pkey) pkey = kk;         // order-independent combine
                ps += sv;
            }
            if (stopK >= 0 || kLow == 0) break;   // inclusive found or chain exhausted
            kHigh = kLow - 1;
        }
    }

    // -- publish inclusive prefix (flag = 2); last chunk has no consumer ------
    if (j < J - 1) {
        g_ikey[b * CC + c] = (lkey > pkey) ? lkey : pkey;  // local later: ties -> prefix
        g_isum[b * CC + c] = ps + ls;
        __syncthreads();
        if (c == 0)
            asm volatile("st.release.gpu.global.b32 [%0], %1;"
                         :: "l"(&g_flag[b]), "r"(2) : "memory");
    }

    // -- phase 3: emit (re-read chunk from L1, scan with exclusive prefix) ----
    float pm; int pa;
    unpack_key(pkey, pm, pa);

    float* optr = out + row0 * OUTW + (size_t)i * 384 + c;
    float* iptr = out + OUT_ELEMS + (size_t)i * NLC + row0 * CC + c;
    float* aptr = iptr + 3 * NLC;
    const float inv_L = 1.0f / (float)LT;

#pragma unroll 4
    for (int t = 0; t < TC; ++t) {
        const int T = j * TC + t;
        float v = p[(size_t)t * CC];
        ps += v;
        if (v > pm) { pm = v; pa = T; }

        const bool pad = (T < LT - 1);            // window still contains left-pad zeros
        float pmax = pad ? fmaxf(pm, 0.f) : pm;
        float ind = (pad && pm < 0.f) ? (float)(T - (LT - 1)) : (float)pa;
        float pavg = ps * inv_L;
        float psum = ps * __frcp_rn((float)(T + 1));

        __stcs(optr, pmax);
        __stcs(optr + 128, pavg);
        __stcs(optr + 256, psum);
        __stcs(iptr, ind);
        __stcs(aptr, pmax);

        optr += OUTW;
        iptr += CC;
        aptr += CC;
    }

    // -- demographic broadcast cols [1152:1172) for this chunk (i==0 only) ----
    if (i == 0) {
#pragma unroll
        for (int q = c; q < TC * 20; q += CC) {
            const int t = q / 20, k = q % 20;
            __stcs(out + (row0 + t) * OUTW + 1152 + k, d_sh[k]);
        }
    }
}

extern "C" void kernel_launch(void* const* d_in, const int* in_sizes, int n_in,
                              void* d_out, int out_size) {
    const float* inp0 = (const float*)d_in[0];
    const float* inp1 = (const float*)d_in[1];
    const float* inp2 = (const float*)d_in[2];
    const float* dem  = (const float*)d_in[3];
    const float* W1   = (const float*)d_in[4];
    const float* b1   = (const float*)d_in[5];
    const float* W2   = (const float*)d_in[6];
    const float* b2   = (const float*)d_in[7];
    float* out = (float*)d_out;

    init_kernel<<<(NCH + 255) / 256, 256>>>();
    dim3 grid(J, NB, 3);                          // j fastest => predecessors launch first
    fused_kernel<<<grid, CC>>>(inp0, inp1, inp2, dem, W1, b1, W2, b2, out);
}

// round 16
// speedup vs baseline: 1.3602x; 1.3602x over previous
#include <cuda_runtime.h>
#include <math_constants.h>

#define NB   32
#define LT   2048
#define CC   128
#define J    64          // chunks along L
#define TC   (LT / J)    // 32 rows per chunk
#define OUTW 1172        // 3*384 + 20
#define NLC  ((size_t)NB * LT * CC)          // 8,388,608
#define OUT_ELEMS ((size_t)NB * LT * OUTW)   // 76,808,192

// chunk aggregates: [3][32][J][128] (c contiguous)
__device__ float g_cmax[3 * NB * J * CC];
__device__ int   g_carg[3 * NB * J * CC];
__device__ float g_csum[3 * NB * J * CC];

// ---------------- pass A: per-chunk aggregates (warp per chunk, float4/lane) --
__global__ void __launch_bounds__(256) agg_kernel(const float* __restrict__ x0,
                                                  const float* __restrict__ x1,
                                                  const float* __restrict__ x2) {
    const int w = threadIdx.x >> 5;
    const int l = threadIdx.x & 31;
    const int j = blockIdx.x * 8 + w;
    const int n = blockIdx.y, i = blockIdx.z;
    const float* x = (i == 0) ? x0 : (i == 1) ? x1 : x2;
    const float4* p = (const float4*)(x + ((size_t)n * LT + (size_t)j * TC) * CC) + l;

    float m0 = -CUDART_INF_F, m1 = m0, m2 = m0, m3 = m0;
    float s0 = 0.f, s1 = 0.f, s2 = 0.f, s3 = 0.f;
    int a0 = 0, a1 = 0, a2 = 0, a3 = 0;
#pragma unroll 8
    for (int t = 0; t < TC; ++t) {
        float4 v = p[t * 32];
        const int T = j * TC + t;
        s0 += v.x; s1 += v.y; s2 += v.z; s3 += v.w;
        if (v.x > m0) { m0 = v.x; a0 = T; }
        if (v.y > m1) { m1 = v.y; a1 = T; }
        if (v.z > m2) { m2 = v.z; a2 = T; }
        if (v.w > m3) { m3 = v.w; a3 = T; }
    }
    const int idx = ((i * NB + n) * J + j) * CC + 4 * l;
    *(float4*)&g_cmax[idx] = make_float4(m0, m1, m2, m3);
    *(int4*)  &g_carg[idx] = make_int4(a0, a1, a2, a3);
    *(float4*)&g_csum[idx] = make_float4(s0, s1, s2, s3);
}

// ---------------- pass B: one block per chunk, 3 groups of 64 (one per input) -
// group i covers stream i with float2 per lane -> each output row is written
// fully (cols 0..1172) by one block for DRAM write locality.
__global__ void __launch_bounds__(192, 8) emit_kernel(const float* __restrict__ x0,
                                                      const float* __restrict__ x1,
                                                      const float* __restrict__ x2,
                                                      const float* __restrict__ dem,
                                                      const float* __restrict__ W1,
                                                      const float* __restrict__ b1,
                                                      const float* __restrict__ W2,
                                                      const float* __restrict__ b2,
                                                      float* __restrict__ out) {
    const int tid = threadIdx.x;
    const int i = tid / 64;                  // input stream
    const int g = tid % 64;                  // lane within group
    const int j = blockIdx.x;                // chunk
    const int n = blockIdx.y;
    const float* x = (i == 0) ? x0 : (i == 1) ? x1 : x2;
    const int c0 = 2 * g;                    // this lane's 2 channels

    // -- demographic MLP (once per block) -------------------------------------
    __shared__ float h_sh[40];
    __shared__ __align__(16) float d_sh[20];
    if (tid < 40) {
        float s = b1[tid];
#pragma unroll
        for (int k = 0; k < 8; ++k) s = fmaf(dem[n * 8 + k], W1[k * 40 + tid], s);
        h_sh[tid] = fmaxf(s, 0.f);
    }
    __syncthreads();
    if (tid < 20) {
        float s = b2[tid];
#pragma unroll
        for (int k = 0; k < 40; ++k) s = fmaf(h_sh[k], W2[k * 20 + tid], s);
        d_sh[tid] = fmaxf(s, 0.f);
    }
    __syncthreads();

    // -- exclusive prefix over earlier chunks (L2-resident aggregates) --------
    float pm0 = -CUDART_INF_F, pm1 = pm0;
    float ps0 = 0.f, ps1 = 0.f;
    int pa0 = 0, pa1 = 0;
    const int base = ((i * NB + n) * J) * CC + c0;
#pragma unroll 4
    for (int k = 0; k < j; ++k) {
        float2 m = *(const float2*)&g_cmax[base + k * CC];
        int2   a = *(const int2*)  &g_carg[base + k * CC];
        float2 s = *(const float2*)&g_csum[base + k * CC];
        if (m.x > pm0) { pm0 = m.x; pa0 = a.x; }
        if (m.y > pm1) { pm1 = m.y; pa1 = a.y; }
        ps0 += s.x; ps1 += s.y;
    }

    const size_t row0 = (size_t)n * LT + (size_t)j * TC;
    const float2* p = (const float2*)(x + row0 * CC + c0);

    float* obase = out + row0 * OUTW + (size_t)i * 384 + c0;
    float* ibase = out + OUT_ELEMS + (size_t)i * NLC + row0 * CC + c0;
    float* abase = ibase + 3 * NLC;

    const float inv_L = 1.0f / (float)LT;

#pragma unroll 4
    for (int t = 0; t < TC; ++t) {
        const int T = j * TC + t;
        float2 v = p[(size_t)t * (CC / 2)];
        ps0 += v.x; ps1 += v.y;
        if (v.x > pm0) { pm0 = v.x; pa0 = T; }
        if (v.y > pm1) { pm1 = v.y; pa1 = T; }

        const bool pad = (T < LT - 1);        // window still contains left-pad zeros
        const float padi = (float)(T - (LT - 1));
        float2 pmax = make_float2(pad ? fmaxf(pm0, 0.f) : pm0,
                                  pad ? fmaxf(pm1, 0.f) : pm1);
        float2 ind = make_float2((pad && pm0 < 0.f) ? padi : (float)pa0,
                                 (pad && pm1 < 0.f) ? padi : (float)pa1);
        float2 pavg = make_float2(ps0 * inv_L, ps1 * inv_L);
        const float rc = __frcp_rn((float)(T + 1));
        float2 psum = make_float2(ps0 * rc, ps1 * rc);

        float* orow = obase + (size_t)t * OUTW;
        __stcs((float2*)(orow),        pmax);
        __stcs((float2*)(orow + 128),  pavg);
        __stcs((float2*)(orow + 256),  psum);
        __stcs((float2*)(ibase + t * CC), ind);
        __stcs((float2*)(abase + t * CC), pmax);
    }

    // -- demographic broadcast cols [1152:1172): group 0 covers the chunk -----
    if (i == 0) {
        float4 dv[5];
#pragma unroll
        for (int q = 0; q < 5; ++q)
            dv[q] = *(const float4*)&d_sh[4 * q];
#pragma unroll
        for (int q = g; q < TC * 5; q += 64) {
            const int t = q / 5, k = q % 5;
            __stcs((float4*)(out + (row0 + t) * OUTW + 1152 + 4 * k), dv[k]);
        }
    }
}

extern "C" void kernel_launch(void* const* d_in, const int* in_sizes, int n_in,
                              void* d_out, int out_size) {
    const float* inp0 = (const float*)d_in[0];
    const float* inp1 = (const float*)d_in[1];
    const float* inp2 = (const float*)d_in[2];
    const float* dem  = (const float*)d_in[3];
    const float* W1   = (const float*)d_in[4];
    const float* b1   = (const float*)d_in[5];
    const float* W2   = (const float*)d_in[6];
    const float* b2   = (const float*)d_in[7];
    float* out = (float*)d_out;

    dim3 agrid(J / 8, NB, 3);    // 8 x 32 x 3 = 768 blocks, warp per chunk
    agg_kernel<<<agrid, 256>>>(inp0, inp1, inp2);
    dim3 egrid(J, NB);           // 64 x 32 = 2048 blocks, full row per block
    emit_kernel<<<egrid, 192>>>(inp0, inp1, inp2, dem, W1, b1, W2, b2, out);
}

// round 17
// speedup vs baseline: 1.3832x; 1.0169x over previous
#include <cuda_runtime.h>
#include <math_constants.h>

#define NB   32
#define LT   2048
#define CC   128
#define J    64          // chunks along L (one block per chunk)
#define TC   (LT / J)    // 32 rows per chunk
#define OUTW 1172        // 3*384 + 20
#define NLC  ((size_t)NB * LT * CC)          // 8,388,608
#define OUT_ELEMS ((size_t)NB * LT * OUTW)   // 76,808,192
#define NCH  (3 * NB * J)                    // 6144 chunk-blocks

// decoupled-lookback state: local aggregates (flag=1) and inclusive prefixes (flag=2)
__device__ float g_lm[NCH * CC], g_ls[NCH * CC], g_im[NCH * CC], g_is[NCH * CC];
__device__ int   g_la[NCH * CC], g_ia[NCH * CC];
__device__ int   g_flag[NCH];

__global__ void init_kernel() {
    int t = blockIdx.x * 256 + threadIdx.x;
    if (t < NCH) g_flag[t] = 0;
}

__global__ void __launch_bounds__(128) fused_kernel(const float* __restrict__ x0,
                                                    const float* __restrict__ x1,
                                                    const float* __restrict__ x2,
                                                    const float* __restrict__ dem,
                                                    const float* __restrict__ W1,
                                                    const float* __restrict__ b1,
                                                    const float* __restrict__ W2,
                                                    const float* __restrict__ b2,
                                                    float* __restrict__ out) {
    // GRID TRANSPOSED: x = chain (fast) so each wave spans ALL chains at the
    // same j-band -> predecessors of later waves are already INCLUSIVE.
    const int chain = blockIdx.x;                 // i*NB + n
    const int j = blockIdx.y;
    const int i = chain / NB, n = chain % NB;
    const int c = threadIdx.x;                    // one channel per thread
    const int l = c & 31;                         // lane
    const float* x = (i == 0) ? x0 : (i == 1) ? x1 : x2;
    const int b = chain * J + j;

    __shared__ float h_sh[40];
    __shared__ float d_sh[20];
    // -- demographic MLP (used by i==0 blocks; recomputed per block) ----------
    if (i == 0 && c < 40) {
        float s = b1[c];
#pragma unroll
        for (int k = 0; k < 8; ++k) s = fmaf(dem[n * 8 + k], W1[k * 40 + c], s);
        h_sh[c] = fmaxf(s, 0.f);
    }
    __syncthreads();
    if (i == 0 && c < 20) {
        float s = b2[c];
#pragma unroll
        for (int k = 0; k < 40; ++k) s = fmaf(h_sh[k], W2[k * 20 + c], s);
        d_sh[c] = fmaxf(s, 0.f);
    }

    // -- phase 1: load my chunk once, compute local aggregate -----------------
    const size_t row0 = (size_t)n * LT + (size_t)j * TC;
    const float* p = x + row0 * CC + c;

    float lm = -CUDART_INF_F, ls = 0.f;
    int la = 0;
#pragma unroll 8
    for (int t = 0; t < TC; ++t) {
        float v = p[(size_t)t * CC];              // allocates in L1 for phase 3
        ls += v;
        if (v > lm) { lm = v; la = j * TC + t; }  // strict > => earliest wins
    }

    // -- publish local aggregate (flag = 1) -----------------------------------
    if (j > 0) {
        g_lm[b * CC + c] = lm;
        g_la[b * CC + c] = la;
        g_ls[b * CC + c] = ls;
        __syncthreads();
        if (c == 0) {
            __threadfence();                      // all block stores visible first
            atomicExch(&g_flag[b], 1);
        }
    }

    // -- parallel-window decoupled lookback: exclusive prefix over 0..j-1 -----
    float pm = -CUDART_INF_F, ps = 0.f;
    int pa = 0;
    if (j > 0) {
        int kHigh = j - 1;
        for (;;) {
            int kLow = kHigh - 31; if (kLow < 0) kLow = 0;
            const int nk = kHigh - kLow + 1;
            const int myk = kHigh - l;
            int f = 0;
            if (l < nk) {
                do { f = *(volatile int*)&g_flag[chain * J + myk]; } while (f == 0);
            }
            const unsigned m2 = __ballot_sync(0xFFFFFFFFu, (l < nk) && (f == 2));
            __threadfence();                      // acquire: value reads ordered after flags
            int stopK = -1;
            if (m2) stopK = kHigh - (__ffs(m2) - 1);   // most recent INCLUSIVE in window
            const int kEnd = (stopK >= 0) ? stopK : kLow;
#pragma unroll 4
            for (int k = kHigh; k >= kEnd; --k) {
                const int idx = (chain * J + k) * CC + c;
                float m, sv; int a;
                if (k == stopK) {
                    m = __ldcg(&g_im[idx]); a = __ldcg(&g_ia[idx]); sv = __ldcg(&g_is[idx]);
                } else {
                    m = __ldcg(&g_lm[idx]); a = __ldcg(&g_la[idx]); sv = __ldcg(&g_ls[idx]);
                }
                if (m >= pm) { pm = m; pa = a; }  // earlier chunk wins ties
                ps += sv;
            }
            if (stopK >= 0 || kLow == 0) break;   // inclusive found or chain exhausted
            kHigh = kLow - 1;
        }
    }

    // -- publish inclusive prefix (flag = 2); last chunk has no consumer ------
    if (j < J - 1) {
        float im = pm, is_ = ps + ls;
        int ia = pa;
        if (lm > pm) { im = lm; ia = la; }        // local later: wins only if strictly >
        g_im[b * CC + c] = im;
        g_ia[b * CC + c] = ia;
        g_is[b * CC + c] = is_;
        __syncthreads();
        if (c == 0) {
            __threadfence();
            atomicExch(&g_flag[b], 2);
        }
    }

    // -- phase 3: emit (re-read chunk from L1, scan with exclusive prefix) ----
    float* optr = out + row0 * OUTW + (size_t)i * 384 + c;
    float* iptr = out + OUT_ELEMS + (size_t)i * NLC + row0 * CC + c;
    float* aptr = iptr + 3 * NLC;
    const float inv_L = 1.0f / (float)LT;

#pragma unroll 4
    for (int t = 0; t < TC; ++t) {
        const int T = j * TC + t;
        float v = p[(size_t)t * CC];
        ps += v;
        if (v > pm) { pm = v; pa = T; }

        const bool pad = (T < LT - 1);            // window still contains left-pad zeros
        float pmax = pad ? fmaxf(pm, 0.f) : pm;
        float ind = (pad && pm < 0.f) ? (float)(T - (LT - 1)) : (float)pa;
        float pavg = ps * inv_L;
        float psum = ps * __frcp_rn((float)(T + 1));

        __stcs(optr, pmax);
        __stcs(optr + 128, pavg);
        __stcs(optr + 256, psum);
        __stcs(iptr, ind);
        __stcs(aptr, pmax);

        optr += OUTW;
        iptr += CC;
        aptr += CC;
    }

    // -- demographic broadcast cols [1152:1172) for this chunk (i==0 only) ----
    if (i == 0) {
#pragma unroll
        for (int q = c; q < TC * 20; q += CC) {
            const int t = q / 20, k = q % 20;
            __stcs(out + (row0 + t) * OUTW + 1152 + k, d_sh[k]);
        }
    }
}

extern "C" void kernel_launch(void* const* d_in, const int* in_sizes, int n_in,
                              void* d_out, int out_size) {
    const float* inp0 = (const float*)d_in[0];
    const float* inp1 = (const float*)d_in[1];
    const float* inp2 = (const float*)d_in[2];
    const float* dem  = (const float*)d_in[3];
    const float* W1   = (const float*)d_in[4];
    const float* b1   = (const float*)d_in[5];
    const float* W2   = (const float*)d_in[6];
    const float* b2   = (const float*)d_in[7];
    float* out = (float*)d_out;

    init_kernel<<<(NCH + 255) / 256, 256>>>();
    dim3 grid(3 * NB, J);        // chain fastest => waves span all chains per j-band
    fused_kernel<<<grid, CC>>>(inp0, inp1, inp2, dem, W1, b1, W2, b2, out);
}